// round 1
// baseline (speedup 1.0000x reference)
#include <cuda_runtime.h>
#include <math.h>

// ---------------------------------------------------------------------------
// Problem constants
// ---------------------------------------------------------------------------
#define Bc  64
#define Dc  2048
#define Hc  4096
#define NSc 25
#define Mc  128              // batched rows: 64 fwd + 64 bwd
#define MH  (Mc * Hc)        // 524288
#define MD  (Mc * Dc)        // 262144

// ---------------------------------------------------------------------------
// Device-global scratch (allocation-free rule)
// ---------------------------------------------------------------------------
__device__ float g_posF[Bc * Dc];
__device__ float g_momF[Bc * Dc];
__device__ float g_posB[Bc * Dc];
__device__ float g_momB[Bc * Dc];
__device__ float g_sldF[Bc];
__device__ float g_sldB[Bc];
__device__ float g_Xa[MD];                 // net input a  (128 x 2048)
__device__ float g_Xb[MD];                 // net input b  (128 x 2048)
__device__ float g_P1[2 * MH];             // layer-1 partials (Xa@W1, Xb@W2)
__device__ float g_P2[2 * MH];             // layer-2 partials (two K-halves)
__device__ float g_P3[6 * MD];             // layer-3 partials: z = half*3 + {S,T,Q}
__device__ float g_bias1[2 * NSc * Hc];    // b1 + t@Wt per (net, step)

// ---------------------------------------------------------------------------
// Init: copy states, build layer-1 biases, build first net input (MOM step)
// ---------------------------------------------------------------------------
__global__ __launch_bounds__(256) void init_k(
    const float* __restrict__ position, const float* __restrict__ momf,
    const float* __restrict__ momb, const float* __restrict__ b1,
    const float* __restrict__ Wt, const float* __restrict__ ts)
{
    int idx = blockIdx.x * blockDim.x + threadIdx.x;
    if (idx < Bc * Dc) {
        float p = position[idx];
        g_posF[idx] = p; g_posB[idx] = p;
        g_momF[idx] = momf[idx]; g_momB[idx] = momb[idx];
    }
    if (idx < MD) {
        int r = idx / Dc, d = idx - r * Dc;
        float p = position[(r & 63) * Dc + d];
        g_Xa[idx] = p;
        g_Xb[idx] = sinf(p);
    }
    if (idx < 2 * NSc * Hc) {
        int h = idx % Hc;
        int s = (idx / Hc) % NSc;
        int n = idx / (Hc * NSc);
        g_bias1[idx] = b1[n * Hc + h]
                     + ts[s * 2 + 0] * Wt[(n * 2 + 0) * Hc + h]
                     + ts[s * 2 + 1] * Wt[(n * 2 + 1) * Hc + h];
    }
    if (idx < Bc) { g_sldF[idx] = 0.f; g_sldB[idx] = 0.f; }
}

// ---------------------------------------------------------------------------
// Tiled fp32 GEMM. BM=128 (all batch rows), BN=64, BK=16, 256 threads,
// per-thread 8x4 microtile. GID selects which stage (A source / activation /
// partial-output) — stage pointers are device globals, weights come as args.
//   GID 1: P1[z] = Xz @ Wz                    (z: 0=Xa@W1, 1=Xb@W2)    K=2048
//   GID 2: P2[z] = relu(P1.0+P1.1+bias1) @ Wh_half[z]                  K=2048
//   GID 3: P3[z] = relu(P2.0+P2.1+bh) @ {Ws,Wtr,Wq}_half   z=half*3+o  K=2048
// ---------------------------------------------------------------------------
struct BP { const float* p[6]; };

template<int GID>
__global__ __launch_bounds__(256) void gemm_k(BP bp, const float* biasArg,
                                              int n, int sF, int sB)
{
    const int z = blockIdx.z;
    const float* A;
    const float* A2 = nullptr;
    const float* bF = nullptr;
    const float* bB = nullptr;
    float* P;
    int k0, lda, N;
    if (GID == 1) {
        A = (z == 0) ? g_Xa : g_Xb;
        P = g_P1 + (size_t)z * MH; k0 = 0; lda = Dc; N = Hc;
    } else if (GID == 2) {
        A  = g_P1; A2 = g_P1 + MH;
        bF = g_bias1 + ((size_t)n * NSc + sF) * Hc;
        bB = g_bias1 + ((size_t)n * NSc + sB) * Hc;
        P = g_P2 + (size_t)z * MH; k0 = z * 2048; lda = Hc; N = Hc;
    } else {
        A  = g_P2; A2 = g_P2 + MH;
        bF = biasArg; bB = biasArg;
        P = g_P3 + (size_t)z * MD; k0 = (z / 3) * 2048; lda = Hc; N = Dc;
    }
    const float* __restrict__ Bm = bp.p[z];
    const int K = 2048;

    __shared__ float As[16][128];
    __shared__ float Bs[16][64];

    const int tid = threadIdx.x;
    const int tm  = tid >> 4;      // 0..15 -> rows tm*8..tm*8+7
    const int tn  = tid & 15;      // 0..15 -> cols tn*4..tn*4+3
    const int bn0 = blockIdx.x * 64;

    float acc[8][4];
#pragma unroll
    for (int i = 0; i < 8; i++)
#pragma unroll
        for (int j = 0; j < 4; j++) acc[i][j] = 0.f;

    for (int kt = 0; kt < K; kt += 16) {
        // --- load A tile (128x16), store transposed, fused activation ---
#pragma unroll
        for (int j = 0; j < 2; j++) {
            int v  = tid + j * 256;          // 0..511
            int m  = v >> 2;                 // 0..127
            int kc = (v & 3) << 2;           // 0,4,8,12
            size_t off = (size_t)m * lda + (size_t)(k0 + kt + kc);
            float4 av = *(const float4*)(A + off);
            float4 r;
            if (GID != 1) {
                float4 bv = *(const float4*)(A2 + off);
                const float* bb = ((m < 64) ? bF : bB) + (k0 + kt + kc);
                float4 cv = *(const float4*)bb;
                r.x = fmaxf(av.x + bv.x + cv.x, 0.f);
                r.y = fmaxf(av.y + bv.y + cv.y, 0.f);
                r.z = fmaxf(av.z + bv.z + cv.z, 0.f);
                r.w = fmaxf(av.w + bv.w + cv.w, 0.f);
            } else {
                r = av;
            }
            As[kc + 0][m] = r.x; As[kc + 1][m] = r.y;
            As[kc + 2][m] = r.z; As[kc + 3][m] = r.w;
        }
        // --- load B tile (16x64) ---
        {
            int k  = tid >> 4;
            int n4 = (tid & 15) << 2;
            *(float4*)&Bs[k][n4] =
                *(const float4*)(Bm + (size_t)(kt + k) * N + (bn0 + n4));
        }
        __syncthreads();

#pragma unroll
        for (int kk = 0; kk < 16; kk++) {
            float a[8], bb[4];
            *(float4*)&a[0] = *(const float4*)&As[kk][tm * 8];
            *(float4*)&a[4] = *(const float4*)&As[kk][tm * 8 + 4];
            *(float4*)&bb[0] = *(const float4*)&Bs[kk][tn * 4];
#pragma unroll
            for (int i = 0; i < 8; i++)
#pragma unroll
                for (int j = 0; j < 4; j++)
                    acc[i][j] = fmaf(a[i], bb[j], acc[i][j]);
        }
        __syncthreads();
    }

#pragma unroll
    for (int i = 0; i < 8; i++) {
        float4 o = make_float4(acc[i][0], acc[i][1], acc[i][2], acc[i][3]);
        *(float4*)(P + (size_t)(tm * 8 + i) * N + (bn0 + tn * 4)) = o;
    }
}

// ---------------------------------------------------------------------------
// Elementwise: S/T/Q epilogue + leapfrog update + logdet rowsum + next-input
// prep, one block per batch row (128 blocks). type: 1=MOM, 0=POS.
// ---------------------------------------------------------------------------
__global__ __launch_bounds__(256) void ep_k(
    int type, const float* __restrict__ eps,
    const float* __restrict__ bs, const float* __restrict__ cs,
    const float* __restrict__ btr, const float* __restrict__ bq,
    const float* __restrict__ cq,
    const float* cmF, int ciF, const float* cmB, int ciB,
    int nextType, const float* nmF, int niF, const float* nmB, int niB)
{
    const int r = blockIdx.x;
    const bool fwd = (r < 64);
    const int sr = fwd ? r : r - 64;
    float* pos = fwd ? g_posF : g_posB;
    float* mom = fwd ? g_momF : g_momB;
    const float* cm = fwd ? cmF : cmB;  const int ci = fwd ? ciF : ciB;
    const float* nm = fwd ? nmF : nmB;  const int ni = fwd ? niF : niB;
    const float e = eps[0];

    float lds = 0.f;
    for (int d = threadIdx.x; d < Dc; d += 256) {
        size_t ro = (size_t)r * Dc + d;
        size_t so = (size_t)sr * Dc + d;
        float Sv = tanhf(g_P3[0 * MD + ro] + g_P3[3 * MD + ro] + bs[d]) * expf(cs[d]);
        float Tv = g_P3[1 * MD + ro] + g_P3[4 * MD + ro] + btr[d];
        float Qv = tanhf(g_P3[2 * MD + ro] + g_P3[5 * MD + ro] + bq[d]) * expf(cq[d]);
        float etr = expf(e * Qv);

        float p = pos[so], v = mom[so];
        if (type == 1) {                       // momentum half-step
            float gg = sinf(p);
            float sc = (fwd ? 0.5f : -0.5f) * e * Sv;
            float es = expf(sc);
            v = fwd ? (v * es - 0.5f * e * (etr * gg - Tv))
                    : (es * (v + 0.5f * e * (etr * gg - Tv)));
            mom[so] = v;
            lds += sc;
        } else {                               // position step (masked)
            float mk = cm[d]; if (ci) mk = 1.f - mk;
            float mi = 1.f - mk;
            float sc = e * Sv;
            float es = expf(sc);
            p = fwd ? (mk * p + mi * (p * es + e * (etr * v + Tv)))
                    : (mk * p + mi * es * (p - e * (etr * v + Tv)));
            pos[so] = p;
            lds += mi * sc;
        }
        // prep next sub-step's net inputs
        if (nextType == 1) {
            g_Xa[ro] = p; g_Xb[ro] = sinf(p);
        } else {
            float k = nm[d]; if (ni) k = 1.f - k;
            g_Xa[ro] = v; g_Xb[ro] = k * p;
        }
    }
    __shared__ float red[256];
    red[threadIdx.x] = lds;
    __syncthreads();
    for (int s2 = 128; s2 > 0; s2 >>= 1) {
        if (threadIdx.x < s2) red[threadIdx.x] += red[threadIdx.x + s2];
        __syncthreads();
    }
    if (threadIdx.x == 0) {
        float* sld = fwd ? g_sldF : g_sldB;
        sld[sr] += red[0];
    }
}

// ---------------------------------------------------------------------------
// Final: hamiltonians, accept prob, output assembly. One block per batch row.
// Output layout: [pos_post (64x2048)][mom_post (64x2048)][ap (64)][pos_out]
// ---------------------------------------------------------------------------
__global__ __launch_bounds__(256) void final_k(
    const float* __restrict__ position, const float* __restrict__ momf0,
    const float* __restrict__ momb0, const float* __restrict__ u_dir,
    const float* __restrict__ u_accept, float* __restrict__ out)
{
    const int b = blockIdx.x;
    float acc7[7] = {0.f, 0.f, 0.f, 0.f, 0.f, 0.f, 0.f};
    for (int d = threadIdx.x; d < Dc; d += 256) {
        size_t o = (size_t)b * Dc + d;
        float x0 = position[o];  acc7[0] += 1.f - cosf(x0);
        float a  = momf0[o];     acc7[1] += 0.5f * a * a;
        float c  = momb0[o];     acc7[2] += 0.5f * c * c;
        float pf = g_posF[o];    acc7[3] += 1.f - cosf(pf);
        float mf = g_momF[o];    acc7[4] += 0.5f * mf * mf;
        float pb = g_posB[o];    acc7[5] += 1.f - cosf(pb);
        float mb = g_momB[o];    acc7[6] += 0.5f * mb * mb;
    }
    __shared__ float red[256];
    __shared__ float tot[7];
    for (int q = 0; q < 7; q++) {
        red[threadIdx.x] = acc7[q];
        __syncthreads();
        for (int s2 = 128; s2 > 0; s2 >>= 1) {
            if (threadIdx.x < s2) red[threadIdx.x] += red[threadIdx.x + s2];
            __syncthreads();
        }
        if (threadIdx.x == 0) tot[q] = red[0];
        __syncthreads();
    }
    __shared__ float s_fm, s_am;
    if (threadIdx.x == 0) {
        float df  = (tot[0] + tot[1]) - (tot[3] + tot[4]) + g_sldF[b];
        float apf = expf(fminf(df, 0.f)); if (!isfinite(apf)) apf = 0.f;
        float db  = (tot[0] + tot[2]) - (tot[5] + tot[6]) + g_sldB[b];
        float apb = expf(fminf(db, 0.f)); if (!isfinite(apb)) apb = 0.f;
        float fm  = (u_dir[b] > 0.5f) ? 1.f : 0.f;
        float ap  = fm * apf + (1.f - fm) * apb;
        out[2 * Bc * Dc + b] = ap;
        s_fm = fm;
        s_am = (ap > u_accept[b]) ? 1.f : 0.f;
    }
    __syncthreads();
    const float fm = s_fm, am = s_am;
    for (int d = threadIdx.x; d < Dc; d += 256) {
        size_t o = (size_t)b * Dc + d;
        float pp = fm * g_posF[o] + (1.f - fm) * g_posB[o];
        float mp = fm * g_momF[o] + (1.f - fm) * g_momB[o];
        out[o] = pp;
        out[(size_t)Bc * Dc + o] = mp;
        out[(size_t)2 * Bc * Dc + Bc + o] = am * pp + (1.f - am) * position[o];
    }
}

// ---------------------------------------------------------------------------
// Host driver
// ---------------------------------------------------------------------------
extern "C" void kernel_launch(void* const* d_in, const int* in_sizes, int n_in,
                              void* d_out, int out_size)
{
    const float* position = (const float*)d_in[0];
    const float* momf     = (const float*)d_in[1];
    const float* momb     = (const float*)d_in[2];
    const float* u_dir    = (const float*)d_in[3];
    const float* u_acc    = (const float*)d_in[4];
    const float* eps      = (const float*)d_in[5];
    const float* masks    = (const float*)d_in[6];
    const float* ts       = (const float*)d_in[7];
    const float* W1       = (const float*)d_in[8];
    const float* W2       = (const float*)d_in[9];
    const float* Wt       = (const float*)d_in[10];
    const float* b1       = (const float*)d_in[11];
    const float* Wh       = (const float*)d_in[12];
    const float* bh       = (const float*)d_in[13];
    const float* Ws       = (const float*)d_in[14];
    const float* bs       = (const float*)d_in[15];
    const float* cs       = (const float*)d_in[16];
    const float* Wtr      = (const float*)d_in[17];
    const float* btr      = (const float*)d_in[18];
    const float* Wq       = (const float*)d_in[19];
    const float* bq       = (const float*)d_in[20];
    const float* cq       = (const float*)d_in[21];
    float* out = (float*)d_out;

    init_k<<<1024, 256>>>(position, momf, momb, b1, Wt, ts);

    const float* sel[3] = {Ws, Wtr, Wq};

    for (int step = 0; step < NSc; step++) {
        const int sF = step, sB = NSc - 1 - step;
        const float* mF = masks + (size_t)sF * Dc;
        const float* mB = masks + (size_t)sB * Dc;

        for (int sub = 0; sub < 4; sub++) {
            const int n = (sub == 0 || sub == 3) ? 1 : 0;  // MOM=1, POS=0

            // GEMM 1: two K=2048 segments (Xa@W1[n], Xb@W2[n])
            BP b1p;
            b1p.p[0] = W1 + (size_t)n * Dc * Hc;
            b1p.p[1] = W2 + (size_t)n * Dc * Hc;
            gemm_k<1><<<dim3(Hc / 64, 1, 2), 256>>>(b1p, nullptr, n, sF, sB);

            // GEMM 2: relu(P1+bias1) @ Wh[n], split-K into 2 halves
            BP b2p;
            b2p.p[0] = Wh + (size_t)n * Hc * Hc;
            b2p.p[1] = Wh + (size_t)n * Hc * Hc + (size_t)2048 * Hc;
            gemm_k<2><<<dim3(Hc / 64, 1, 2), 256>>>(b2p, nullptr, n, sF, sB);

            // GEMM 3: relu(P2+bh) @ {Ws,Wtr,Wq}[n], 3 outputs x 2 K-halves
            BP b3p;
            for (int zz = 0; zz < 6; zz++) {
                int o = zz % 3, half = zz / 3;
                b3p.p[zz] = sel[o] + (size_t)n * Hc * Dc + (size_t)half * 2048 * Dc;
            }
            gemm_k<3><<<dim3(Dc / 64, 1, 6), 256>>>(b3p, bh + (size_t)n * Hc,
                                                    n, sF, sB);

            // Elementwise update + next-input prep
            int type, nextType;
            const float *cmF = nullptr, *cmB = nullptr, *nmF = nullptr, *nmB = nullptr;
            int ciF = 0, ciB = 0, niF = 0, niB = 0;
            if (sub == 0) {        // MOM; next POS (fwd: m, bwd: 1-m)
                type = 1; nextType = 0;
                nmF = mF; niF = 0; nmB = mB; niB = 1;
            } else if (sub == 1) { // POS (fwd m / bwd 1-m); next POS swapped
                type = 0; nextType = 0;
                cmF = mF; ciF = 0; cmB = mB; ciB = 1;
                nmF = mF; niF = 1; nmB = mB; niB = 0;
            } else if (sub == 2) { // POS (fwd 1-m / bwd m); next MOM
                type = 0; nextType = 1;
                cmF = mF; ciF = 1; cmB = mB; ciB = 0;
            } else {               // MOM; next MOM (next step's sub0)
                type = 1; nextType = 1;
            }
            ep_k<<<128, 256>>>(type, eps,
                               bs + (size_t)n * Dc, cs + (size_t)n * Dc,
                               btr + (size_t)n * Dc, bq + (size_t)n * Dc,
                               cq + (size_t)n * Dc,
                               cmF, ciF, cmB, ciB,
                               nextType, nmF, niF, nmB, niB);
        }
    }

    final_k<<<64, 256>>>(position, momf, momb, u_dir, u_acc, out);
}